// round 4
// baseline (speedup 1.0000x reference)
#include <cuda_runtime.h>
#include <math.h>
#include <limits.h>

#define LROW 2048
#define SDIM 65
#define OUT_PER_ROW (SDIM * SDIM)   // 4225
#define THRESH 0.2f
#define EPSV 1e-6f
#define NTHREADS 256
#define MAX_ROWS 16384

// Scratch: normalized first-65 values per row (NaN sentinel = invalid position)
__device__ float g_ys[MAX_ROWS * SDIM];

// ============================================================================
// Kernel 1: read-dominant. Row stats + normalized first 65 -> scratch.
// Traffic: 128 MB read, 4.3 MB write.
// ============================================================================
__global__ __launch_bounds__(NTHREADS, 8)
void stats_kernel(const float* __restrict__ x) {
    const int row = blockIdx.x;
    const int t = threadIdx.x;
    const float4* __restrict__ xr =
        reinterpret_cast<const float4*>(x + (size_t)row * LROW);

    const float4 v0 = __ldcs(&xr[t]);            // idx 4t..4t+3 (t<17 holds first 68)
    const float4 v1 = __ldcs(&xr[t + NTHREADS]);

    float sum = 0.f, sumsq = 0.f;
    int mn = INT_MAX, mx = -1;
    {
        const float4 v = v0; const int base = t * 4;
        sum   += (v.x + v.y) + (v.z + v.w);
        sumsq += (v.x * v.x + v.y * v.y) + (v.z * v.z + v.w * v.w);
        if (v.x != 0.f) { mn = min(mn, base + 0); mx = max(mx, base + 0); }
        if (v.y != 0.f) { mn = min(mn, base + 1); mx = max(mx, base + 1); }
        if (v.z != 0.f) { mn = min(mn, base + 2); mx = max(mx, base + 2); }
        if (v.w != 0.f) { mn = min(mn, base + 3); mx = max(mx, base + 3); }
    }
    {
        const float4 v = v1; const int base = (t + NTHREADS) * 4;
        sum   += (v.x + v.y) + (v.z + v.w);
        sumsq += (v.x * v.x + v.y * v.y) + (v.z * v.z + v.w * v.w);
        if (v.x != 0.f) { mn = min(mn, base + 0); mx = max(mx, base + 0); }
        if (v.y != 0.f) { mn = min(mn, base + 1); mx = max(mx, base + 1); }
        if (v.z != 0.f) { mn = min(mn, base + 2); mx = max(mx, base + 2); }
        if (v.w != 0.f) { mn = min(mn, base + 3); mx = max(mx, base + 3); }
    }

    #pragma unroll
    for (int o = 16; o > 0; o >>= 1) {
        sum   += __shfl_down_sync(0xffffffffu, sum, o);
        sumsq += __shfl_down_sync(0xffffffffu, sumsq, o);
        mn = min(mn, __shfl_down_sync(0xffffffffu, mn, o));
        mx = max(mx, __shfl_down_sync(0xffffffffu, mx, o));
    }

    __shared__ float s_sum[8], s_sq[8];
    __shared__ int   s_mn[8],  s_mx[8];
    const int wid = t >> 5, lid = t & 31;
    if (lid == 0) { s_sum[wid] = sum; s_sq[wid] = sumsq; s_mn[wid] = mn; s_mx[wid] = mx; }
    __syncthreads();

    __shared__ float s_mean, s_rstd;
    __shared__ int   s_start, s_end;
    if (t < 32) {
        sum   = (t < 8) ? s_sum[t] : 0.f;
        sumsq = (t < 8) ? s_sq[t]  : 0.f;
        mn    = (t < 8) ? s_mn[t]  : INT_MAX;
        mx    = (t < 8) ? s_mx[t]  : -1;
        #pragma unroll
        for (int o = 4; o > 0; o >>= 1) {
            sum   += __shfl_down_sync(0xffffffffu, sum, o);
            sumsq += __shfl_down_sync(0xffffffffu, sumsq, o);
            mn = min(mn, __shfl_down_sync(0xffffffffu, mn, o));
            mx = max(mx, __shfl_down_sync(0xffffffffu, mx, o));
        }
        if (t == 0) {
            const float cnt  = (mx >= 0) ? (float)(mx - mn + 1) : 1.f;
            const float mean = sum / cnt;
            const float var  = fmaxf(sumsq / cnt - mean * mean, 0.f);
            const float stdv = fmaxf(sqrtf(var), EPSV);
            s_mean = mean;
            s_rstd = 1.f / stdv;
            s_start = mn;
            s_end   = mx;
        }
    }
    __syncthreads();

    // normalized first 65 from registers -> scratch (NaN = invalid)
    if (t < 17) {
        const float vals[4] = {v0.x, v0.y, v0.z, v0.w};
        const float mean = s_mean, rstd = s_rstd;
        const int st = s_start, en = s_end;
        float* __restrict__ yrow = g_ys + (size_t)row * SDIM;
        #pragma unroll
        for (int e = 0; e < 4; e++) {
            const int idx = 4 * t + e;
            if (idx < SDIM) {
                const bool valid = (idx >= st) && (idx <= en);
                yrow[idx] = valid ? (vals[e] - mean) * rstd
                                  : __int_as_float(0x7fffffff);
            }
        }
    }
}

// ============================================================================
// Kernel 2: write-pure. ys (L2-resident) -> 65x65 matrix, streamed to DRAM.
// Traffic: ~4.3 MB read (L2 hit), 277 MB write.
// ============================================================================
__global__ __launch_bounds__(NTHREADS, 8)
void matrix_kernel(float* __restrict__ out) {
    const int row = blockIdx.x;
    const int t = threadIdx.x;

    // duplicated ys: ysd[m] = ys[m % 65] for m < 130 (no wrap arithmetic later)
    __shared__ float ysd[132];
    if (t < SDIM) {
        const float yv = g_ys[(size_t)row * SDIM + t];
        ysd[t] = yv;
        ysd[t + SDIM] = yv;
    }
    __syncthreads();

    float* __restrict__ orow = out + (size_t)row * OUT_PER_ROW;
    const int s = (4 - (row & 3)) & 3;          // head scalars for 16B alignment
    const int m = (OUT_PER_ROW - s) >> 2;
    const int tail = s + 4 * m;

    if (t == 0) {
        for (int k = 0; k < s; k++) {
            const unsigned i = (unsigned)k / 65u;
            const unsigned j = (unsigned)k - i * 65u;
            __stcs(&orow[k], (fabsf(ysd[i] - ysd[j]) < THRESH) ? 1.f : 0.f);
        }
    }
    if (t == 1) {
        for (int k = tail; k < OUT_PER_ROW; k++) {
            const unsigned i = (unsigned)k / 65u;
            const unsigned j = (unsigned)k - i * 65u;
            __stcs(&orow[k], (fabsf(ysd[i] - ysd[j]) < THRESH) ? 1.f : 0.f);
        }
    }

    #pragma unroll 4
    for (int g = t; g < m; g += NTHREADS) {
        const int k = s + 4 * g;                     // 16B-aligned global index
        const unsigned i = (unsigned)k / 65u;
        const unsigned j = (unsigned)k - i * 65u;    // 0..64
        const float yi0 = ysd[i];
        const float yi1 = ysd[i + 1];
        const unsigned thr = 65u - j;                // e >= thr <=> row wrap
        const float a0 = ysd[j];
        const float a1 = ysd[j + 1];
        const float a2 = ysd[j + 2];
        const float a3 = ysd[j + 3];
        float4 o;
        o.x = (fabsf(yi0 - a0) < THRESH) ? 1.f : 0.f;
        o.y = (fabsf(((1u >= thr) ? yi1 : yi0) - a1) < THRESH) ? 1.f : 0.f;
        o.z = (fabsf(((2u >= thr) ? yi1 : yi0) - a2) < THRESH) ? 1.f : 0.f;
        o.w = (fabsf(((3u >= thr) ? yi1 : yi0) - a3) < THRESH) ? 1.f : 0.f;
        __stcs(reinterpret_cast<float4*>(&orow[k]), o);
    }
}

extern "C" void kernel_launch(void* const* d_in, const int* in_sizes, int n_in,
                              void* d_out, int out_size) {
    const float* x = (const float*)d_in[0];
    float* out = (float*)d_out;
    const int nrows = in_sizes[0] / LROW;   // 16384
    stats_kernel<<<nrows, NTHREADS>>>(x);
    matrix_kernel<<<nrows, NTHREADS>>>(out);
}

// round 5
// speedup vs baseline: 1.1299x; 1.1299x over previous
#include <cuda_runtime.h>
#include <math.h>
#include <limits.h>

#define LROW 2048
#define SDIM 65
#define OUT_PER_ROW (SDIM * SDIM)   // 4225
#define THRESH 0.2f
#define EPSV 1e-6f
#define NTHREADS 256

__global__ __launch_bounds__(NTHREADS, 8)
void rp_kernel(const float* __restrict__ x, float* __restrict__ out) {
    const int row = blockIdx.x;
    const int t = threadIdx.x;
    const float4* __restrict__ xr =
        reinterpret_cast<const float4*>(x + (size_t)row * LROW);

    // ---- one-pass row stats: sum, sumsq, min/max nonzero index ----
    const float4 v0 = __ldcs(&xr[t]);            // idx 4t..4t+3 (t<17 holds first 68)
    const float4 v1 = __ldcs(&xr[t + NTHREADS]);

    float sum = 0.f, sumsq = 0.f;
    int mn = INT_MAX, mx = -1;
    {
        const float4 v = v0; const int base = t * 4;
        sum   += (v.x + v.y) + (v.z + v.w);
        sumsq += (v.x * v.x + v.y * v.y) + (v.z * v.z + v.w * v.w);
        if (v.x != 0.f) { mn = min(mn, base + 0); mx = max(mx, base + 0); }
        if (v.y != 0.f) { mn = min(mn, base + 1); mx = max(mx, base + 1); }
        if (v.z != 0.f) { mn = min(mn, base + 2); mx = max(mx, base + 2); }
        if (v.w != 0.f) { mn = min(mn, base + 3); mx = max(mx, base + 3); }
    }
    {
        const float4 v = v1; const int base = (t + NTHREADS) * 4;
        sum   += (v.x + v.y) + (v.z + v.w);
        sumsq += (v.x * v.x + v.y * v.y) + (v.z * v.z + v.w * v.w);
        if (v.x != 0.f) { mn = min(mn, base + 0); mx = max(mx, base + 0); }
        if (v.y != 0.f) { mn = min(mn, base + 1); mx = max(mx, base + 1); }
        if (v.z != 0.f) { mn = min(mn, base + 2); mx = max(mx, base + 2); }
        if (v.w != 0.f) { mn = min(mn, base + 3); mx = max(mx, base + 3); }
    }

    // ---- warp reduce ----
    #pragma unroll
    for (int o = 16; o > 0; o >>= 1) {
        sum   += __shfl_down_sync(0xffffffffu, sum, o);
        sumsq += __shfl_down_sync(0xffffffffu, sumsq, o);
        mn = min(mn, __shfl_down_sync(0xffffffffu, mn, o));
        mx = max(mx, __shfl_down_sync(0xffffffffu, mx, o));
    }

    __shared__ float s_sum[8], s_sq[8];
    __shared__ int   s_mn[8],  s_mx[8];
    const int wid = t >> 5, lid = t & 31;
    if (lid == 0) { s_sum[wid] = sum; s_sq[wid] = sumsq; s_mn[wid] = mn; s_mx[wid] = mx; }
    __syncthreads();

    __shared__ float s_mean, s_rstd;
    __shared__ int   s_start, s_end;
    if (t < 32) {
        sum   = (t < 8) ? s_sum[t] : 0.f;
        sumsq = (t < 8) ? s_sq[t]  : 0.f;
        mn    = (t < 8) ? s_mn[t]  : INT_MAX;
        mx    = (t < 8) ? s_mx[t]  : -1;
        #pragma unroll
        for (int o = 4; o > 0; o >>= 1) {
            sum   += __shfl_down_sync(0xffffffffu, sum, o);
            sumsq += __shfl_down_sync(0xffffffffu, sumsq, o);
            mn = min(mn, __shfl_down_sync(0xffffffffu, mn, o));
            mx = max(mx, __shfl_down_sync(0xffffffffu, mx, o));
        }
        if (t == 0) {
            const float cnt  = (mx >= 0) ? (float)(mx - mn + 1) : 1.f;
            const float mean = sum / cnt;
            const float var  = fmaxf(sumsq / cnt - mean * mean, 0.f);
            const float stdv = fmaxf(sqrtf(var), EPSV);
            s_mean = mean;
            s_rstd = 1.f / stdv;
            s_start = mn;
            s_end   = mx;
        }
    }
    __syncthreads();

    // ---- normalized first 65 values from registers (NaN = invalid mask) ----
    __shared__ float ys[SDIM];
    if (t < 17) {
        const float vals[4] = {v0.x, v0.y, v0.z, v0.w};
        const float mean = s_mean, rstd = s_rstd;
        const int st = s_start, en = s_end;
        #pragma unroll
        for (int e = 0; e < 4; e++) {
            const int idx = 4 * t + e;
            if (idx < SDIM) {
                const bool valid = (idx >= st) && (idx <= en);
                ys[idx] = valid ? (vals[e] - mean) * rstd
                                : __int_as_float(0x7fffffff);
            }
        }
    }
    __syncthreads();

    // ---- 65x65 matrix: warp-per-output-row, comparands in registers ----
    // Lane l holds ya=ys[l], yb=ys[l+32], yc=ys[64]: zero conflicted LDS in loop.
    // Per row: 1 broadcast LDS (yi) + 2 coalesced warp STG.32 + 1 lane STG.32.
    float* __restrict__ orow = out + (size_t)row * OUT_PER_ROW;
    const float ya = ys[lid];            // j = lid        (conflict-free)
    const float yb = ys[lid + 32];       // j = lid + 32   (conflict-free)
    const float yc = ys[SDIM - 1];       // j = 64         (broadcast)

    #pragma unroll 3
    for (int i = wid; i < SDIM; i += 8) {
        const float yi = ys[i];          // uniform per warp -> broadcast
        float* __restrict__ oi = orow + i * SDIM;
        __stcs(&oi[lid],      (fabsf(yi - ya) < THRESH) ? 1.f : 0.f);
        __stcs(&oi[lid + 32], (fabsf(yi - yb) < THRESH) ? 1.f : 0.f);
        if (lid == 0)
            __stcs(&oi[64],   (fabsf(yi - yc) < THRESH) ? 1.f : 0.f);
    }
}

extern "C" void kernel_launch(void* const* d_in, const int* in_sizes, int n_in,
                              void* d_out, int out_size) {
    const float* x = (const float*)d_in[0];
    float* out = (float*)d_out;
    const int nrows = in_sizes[0] / LROW;   // 1024*16 = 16384
    rp_kernel<<<nrows, NTHREADS>>>(x, out);
}